// round 1
// baseline (speedup 1.0000x reference)
#include <cuda_runtime.h>
#include <cuda_bf16.h>
#include <cstddef>

// Problem constants (fixed shapes for this problem instance)
#define BB 32
#define TT 2048
#define DD 256
#define CHUNK 128
#define NCHUNK (TT / CHUNK)   // 16

// Scratch: exclusive prefix sums csum[B, T+1, D]  (allocation-free: device global)
__device__ float g_csum[(size_t)BB * (TT + 1) * DD];
// Scratch: per-chunk partial sums part[B, NCHUNK, D]
__device__ float g_part[(size_t)BB * NCHUNK * DD];

// ---------------------------------------------------------------------------
// Kernel A: per-chunk partial sums. grid = (NCHUNK, B), block = D threads.
// Thread d sums token_embs[b, c*CHUNK .. c*CHUNK+CHUNK, d].
// ---------------------------------------------------------------------------
__global__ void pe_partial(const float* __restrict__ x) {
    const int d = threadIdx.x;
    const int c = blockIdx.x;
    const int b = blockIdx.y;
    const float* p = x + ((size_t)b * TT + (size_t)c * CHUNK) * DD + d;
    float s = 0.0f;
#pragma unroll 8
    for (int i = 0; i < CHUNK; i++) s += p[(size_t)i * DD];
    g_part[((size_t)b * NCHUNK + c) * DD + d] = s;
}

// ---------------------------------------------------------------------------
// Kernel B: write exclusive csum. grid = (NCHUNK, B), block = D threads.
// csum[b, t, d] = sum of token rows [0, t).  Also writes csum[b, T, d].
// ---------------------------------------------------------------------------
__global__ void pe_scan_write(const float* __restrict__ x) {
    const int d = threadIdx.x;
    const int c = blockIdx.x;
    const int b = blockIdx.y;

    float base = 0.0f;
#pragma unroll
    for (int k = 0; k < NCHUNK; k++) {
        if (k < c) base += g_part[((size_t)b * NCHUNK + k) * DD + d];
    }

    const float* p = x + ((size_t)b * TT + (size_t)c * CHUNK) * DD + d;
    float* q = g_csum + ((size_t)b * (TT + 1) + (size_t)c * CHUNK) * DD + d;

    float run = base;
#pragma unroll 8
    for (int i = 0; i < CHUNK; i++) {
        q[(size_t)i * DD] = run;
        run += p[(size_t)i * DD];
    }
    if (c == NCHUNK - 1) {
        q[(size_t)CHUNK * DD] = run;   // csum[b, T, d]
    }
}

// ---------------------------------------------------------------------------
// Kernel C: gather. One warp per (pair, half). 2P warp-tasks.
// out[p, half*D : half*D+D] = (csum[b, start+span] - csum[b, start]) / span
// D=256 floats = 64 float4 per row; each lane handles 2 float4.
// ---------------------------------------------------------------------------
__global__ void pe_gather(const int* __restrict__ p1_start,
                          const int* __restrict__ p1_span,
                          const int* __restrict__ p2_start,
                          const int* __restrict__ p2_span,
                          const int* __restrict__ pair_batch,
                          float* __restrict__ out,
                          int n_pairs) {
    const int warp_in_block = threadIdx.x >> 5;
    const int lane = threadIdx.x & 31;
    const int task = blockIdx.x * (blockDim.x >> 5) + warp_in_block;
    if (task >= 2 * n_pairs) return;

    const int p    = task >> 1;
    const int half = task & 1;

    const int start = half ? p2_start[p] : p1_start[p];
    const int span  = half ? p2_span[p]  : p1_span[p];
    const int b     = pair_batch[p];

    const float inv = 1.0f / (float)span;

    const float4* cs = (const float4*)(g_csum + (size_t)b * (TT + 1) * DD);
    const float4* re = cs + (size_t)(start + span) * (DD / 4);
    const float4* rs = cs + (size_t)start * (DD / 4);

    float4 e0 = re[lane];
    float4 s0 = rs[lane];
    float4 e1 = re[lane + 32];
    float4 s1 = rs[lane + 32];

    float4 o0, o1;
    o0.x = (e0.x - s0.x) * inv;  o0.y = (e0.y - s0.y) * inv;
    o0.z = (e0.z - s0.z) * inv;  o0.w = (e0.w - s0.w) * inv;
    o1.x = (e1.x - s1.x) * inv;  o1.y = (e1.y - s1.y) * inv;
    o1.z = (e1.z - s1.z) * inv;  o1.w = (e1.w - s1.w) * inv;

    float4* o = (float4*)out + (size_t)p * (2 * DD / 4) + (size_t)half * (DD / 4);
    o[lane]      = o0;
    o[lane + 32] = o1;
}

// ---------------------------------------------------------------------------
extern "C" void kernel_launch(void* const* d_in, const int* in_sizes, int n_in,
                              void* d_out, int out_size) {
    const float* token_embs = (const float*)d_in[0];
    const int*   p1_start   = (const int*)d_in[1];
    const int*   p1_span    = (const int*)d_in[2];
    const int*   p2_start   = (const int*)d_in[3];
    const int*   p2_span    = (const int*)d_in[4];
    const int*   pair_batch = (const int*)d_in[5];
    float*       out        = (float*)d_out;

    const int P = in_sizes[1];

    dim3 gridAB(NCHUNK, BB);
    pe_partial<<<gridAB, DD>>>(token_embs);
    pe_scan_write<<<gridAB, DD>>>(token_embs);

    const int warps_per_block = 4;                       // 128 threads
    const int tasks = 2 * P;
    const int blocks = (tasks + warps_per_block - 1) / warps_per_block;
    pe_gather<<<blocks, warps_per_block * 32>>>(p1_start, p1_span, p2_start,
                                                p2_span, pair_batch, out, P);
}

// round 2
// speedup vs baseline: 1.0050x; 1.0050x over previous
#include <cuda_runtime.h>
#include <cuda_bf16.h>
#include <cstddef>

// Problem constants (fixed shapes for this problem instance)
#define BB 32
#define TT 2048
#define DD 256
#define D4 (DD / 4)           // 64 float4 per row
#define CHUNK 32
#define NCHUNK (TT / CHUNK)   // 64

// Scratch: exclusive prefix sums csum[B, T+1, D]  (allocation-free: device global)
__device__ float g_csum[(size_t)BB * (TT + 1) * DD];
// Scratch: per-chunk partial sums part[B, NCHUNK, D] (becomes exclusive chunk prefix)
__device__ float g_part[(size_t)BB * NCHUNK * DD];

__device__ __forceinline__ float4 f4add(float4 a, float4 b) {
    return make_float4(a.x + b.x, a.y + b.y, a.z + b.z, a.w + b.w);
}

// ---------------------------------------------------------------------------
// K1: per-chunk partial sums. grid = (NCHUNK, B), block = 64 threads (one
// float4 column each). 32 independent float4 loads per thread -> high MLP.
// ---------------------------------------------------------------------------
__global__ void pe_partial(const float4* __restrict__ x) {
    const int l = threadIdx.x;          // 0..63 float4 lane
    const int c = blockIdx.x;
    const int b = blockIdx.y;
    const float4* p = x + ((size_t)b * TT + (size_t)c * CHUNK) * D4 + l;
    float4 s0 = make_float4(0.f, 0.f, 0.f, 0.f);
    float4 s1 = make_float4(0.f, 0.f, 0.f, 0.f);
#pragma unroll
    for (int i = 0; i < CHUNK; i += 2) {
        s0 = f4add(s0, p[(size_t)i * D4]);
        s1 = f4add(s1, p[(size_t)(i + 1) * D4]);
    }
    ((float4*)g_part)[((size_t)b * NCHUNK + c) * D4 + l] = f4add(s0, s1);
}

// ---------------------------------------------------------------------------
// K2: exclusive scan of chunk partials (in place). grid = B, block = 64.
// Tiny: 2 MB read + 2 MB write, all L2.
// ---------------------------------------------------------------------------
__global__ void pe_chunkscan() {
    const int l = threadIdx.x;
    const int b = blockIdx.x;
    float4* part = (float4*)g_part + (size_t)b * NCHUNK * D4 + l;
    float4 run = make_float4(0.f, 0.f, 0.f, 0.f);
#pragma unroll
    for (int k = 0; k < NCHUNK; k++) {
        float4 v = part[(size_t)k * D4];
        part[(size_t)k * D4] = run;
        run = f4add(run, v);
    }
}

// ---------------------------------------------------------------------------
// K3: write exclusive csum. grid = (NCHUNK, B), block = 64 threads (float4).
// base comes from the pre-scanned g_part; per-thread serial scan of 32 rows.
// ---------------------------------------------------------------------------
__global__ void pe_scan_write(const float4* __restrict__ x) {
    const int l = threadIdx.x;
    const int c = blockIdx.x;
    const int b = blockIdx.y;

    float4 run = ((const float4*)g_part)[((size_t)b * NCHUNK + c) * D4 + l];

    const float4* p = x + ((size_t)b * TT + (size_t)c * CHUNK) * D4 + l;
    float4* q = (float4*)g_csum + ((size_t)b * (TT + 1) + (size_t)c * CHUNK) * D4 + l;

#pragma unroll
    for (int i = 0; i < CHUNK; i++) {
        q[(size_t)i * D4] = run;
        run = f4add(run, p[(size_t)i * D4]);
    }
    if (c == NCHUNK - 1) {
        q[(size_t)CHUNK * D4] = run;   // csum[b, T, :]
    }
}

// ---------------------------------------------------------------------------
// K4: gather. One warp per (pair, half). 2P warp-tasks.
// out[p, half*D : half*D+D] = (csum[b, start+span] - csum[b, start]) / span
// ---------------------------------------------------------------------------
__global__ void pe_gather(const int* __restrict__ p1_start,
                          const int* __restrict__ p1_span,
                          const int* __restrict__ p2_start,
                          const int* __restrict__ p2_span,
                          const int* __restrict__ pair_batch,
                          float* __restrict__ out,
                          int n_pairs) {
    const int warp_in_block = threadIdx.x >> 5;
    const int lane = threadIdx.x & 31;
    const int task = blockIdx.x * (blockDim.x >> 5) + warp_in_block;
    if (task >= 2 * n_pairs) return;

    const int p    = task >> 1;
    const int half = task & 1;

    const int start = half ? p2_start[p] : p1_start[p];
    const int span  = half ? p2_span[p]  : p1_span[p];
    const int b     = pair_batch[p];

    const float inv = 1.0f / (float)span;

    const float4* cs = (const float4*)g_csum + (size_t)b * (TT + 1) * D4;
    const float4* re = cs + (size_t)(start + span) * D4;
    const float4* rs = cs + (size_t)start * D4;

    float4 e0 = re[lane];
    float4 s0 = rs[lane];
    float4 e1 = re[lane + 32];
    float4 s1 = rs[lane + 32];

    float4 o0, o1;
    o0.x = (e0.x - s0.x) * inv;  o0.y = (e0.y - s0.y) * inv;
    o0.z = (e0.z - s0.z) * inv;  o0.w = (e0.w - s0.w) * inv;
    o1.x = (e1.x - s1.x) * inv;  o1.y = (e1.y - s1.y) * inv;
    o1.z = (e1.z - s1.z) * inv;  o1.w = (e1.w - s1.w) * inv;

    float4* o = (float4*)out + (size_t)p * (2 * D4) + (size_t)half * D4;
    o[lane]      = o0;
    o[lane + 32] = o1;
}

// ---------------------------------------------------------------------------
extern "C" void kernel_launch(void* const* d_in, const int* in_sizes, int n_in,
                              void* d_out, int out_size) {
    const float4* token_embs = (const float4*)d_in[0];
    const int*    p1_start   = (const int*)d_in[1];
    const int*    p1_span    = (const int*)d_in[2];
    const int*    p2_start   = (const int*)d_in[3];
    const int*    p2_span    = (const int*)d_in[4];
    const int*    pair_batch = (const int*)d_in[5];
    float*        out        = (float*)d_out;

    const int P = in_sizes[1];

    dim3 gridCB(NCHUNK, BB);
    pe_partial<<<gridCB, 64>>>(token_embs);
    pe_chunkscan<<<BB, 64>>>();
    pe_scan_write<<<gridCB, 64>>>(token_embs);

    const int warps_per_block = 8;                       // 256 threads
    const int tasks = 2 * P;
    const int blocks = (tasks + warps_per_block - 1) / warps_per_block;
    pe_gather<<<blocks, warps_per_block * 32>>>(p1_start, p1_span, p2_start,
                                                p2_span, pair_batch, out, P);
}